// round 10
// baseline (speedup 1.0000x reference)
#include <cuda_runtime.h>

// _QuantumLSTMCell: analytic collapse of the 4-qubit circuit.
// angles = comb @ W^T + b ; z_w = cos(angle_w + th_w)
// E0 = z1 z2 z3 ; E1 = z0 z1 ; E2 = z0 z1 z2 ; E3 = z0 z1 z2 z3
// f,i,o = sigmoid(E), g = tanh(E_u); c' = f*cx + i*g; h' = o*tanh(c')
// out = [h_new (B*4) | c_new (B*4)]
//
// R10: TILE_K=32 (full 128-B line per row per tile -> DRAM efficiency),
// 64-thread CTAs (grid 1024, ~5 CTAs/SM), k-parity packing everywhere:
// constant image = RAW W_f/W_i bytes (no repack kernel, direct D2D
// memcpyToSymbol), smem u/o weights as [kp][8] u64, zero x-splats.

#define THREADS 64
#define WARPS 2
#define RPT 2
#define ROWS_WARP 64                 // 32 lanes * RPT
#define ROWS_BLK (WARPS * ROWS_WARP) // 128
#define D_COLS 256
#define NJ 16
#define TILE_K 32
#define NTILES (D_COLS / TILE_K)     // 8
#define PITCH 36                     // floats per staged row (36%32==4 -> phase-distinct)
#define XS_WARP_F (ROWS_WARP * PITCH)    // 2304 floats per warp per stage
#define SW8_U 1040                   // 130 kp * 8 j  (u64 entries)
#define SMEM_BYTES (SW8_U * 8 + WARPS * 2 * XS_WARP_F * 4 + 64)  // 45,312 B

typedef unsigned long long u64;

// raw f,i weight image: floats [0..1039]=W_f[4][260], [1040..2079]=W_i[4][260]
__constant__ float cW[2080];

__device__ __forceinline__ u64 pk(float lo, float hi) {
    u64 r; asm("mov.b64 %0, {%1,%2};" : "=l"(r) : "f"(lo), "f"(hi)); return r;
}
__device__ __forceinline__ void upk(u64 v, float& lo, float& hi) {
    asm("mov.b64 {%0,%1}, %2;" : "=f"(lo), "=f"(hi) : "l"(v));
}
__device__ __forceinline__ void fma2(u64& d, u64 a, u64 b) {
    asm("fma.rn.f32x2 %0, %1, %2, %0;" : "+l"(d) : "l"(a), "l"(b));
}
__device__ __forceinline__ void cp16(unsigned dst, const void* src) {
    asm volatile("cp.async.cg.shared.global [%0], [%1], 16;" :: "r"(dst), "l"(src));
}
__device__ __forceinline__ void cp_commit() {
    asm volatile("cp.async.commit_group;");
}
__device__ __forceinline__ void cp_wait1() {
    asm volatile("cp.async.wait_group 1;");
}
__device__ __forceinline__ void cp_wait0() {
    asm volatile("cp.async.wait_group 0;");
}

__device__ __forceinline__ float sigmoidf_(float x) {
    return 1.0f / (1.0f + __expf(-x));
}
__device__ __forceinline__ float tanhf_(float x) {
    return 1.0f - 2.0f / (__expf(2.0f * x) + 1.0f);
}

// issue one TILE_K=32 tile (64 rows x 128 B) for this warp: 16 cp16 instrs,
// each instr = 8 rows x 64 B contiguous; the h=0/1 pair completes full lines.
__device__ __forceinline__ void issue_tile(unsigned xs_s, const float* xw,
                                           int lane, int tile, int slot) {
#pragma unroll
    for (int i = 0; i < 16; i++) {
        int p = i >> 1, h = i & 1;
        int rl = p * 8 + (lane >> 2);
        int ch = h * 4 + (lane & 3);
        cp16(xs_s + (unsigned)((slot * XS_WARP_F + rl * PITCH + ch * 4) * 4),
             xw + (size_t)rl * D_COLS + tile * TILE_K + ch * 4);
    }
    cp_commit();
}

// process one float4 (= 2 k-pairs) for both rows against all 16 j.
// xq[r] = (kp0 pair, kp1 pair) as two u64. Const j0..7 (k-parity in raw
// layout), smem j8..15 ([kp][8] u64).
__device__ __forceinline__ void do_group(u64 accC[RPT][8], u64 accS[RPT][8],
                                         const ulonglong2 xq[RPT],
                                         int k0, const ulonglong2* __restrict__ sw8v) {
    // constant half: j0..3 = f gates w0..3 (row j*260), j4..7 = i gates
#pragma unroll
    for (int j = 0; j < 8; j++) {
        ulonglong2 w = *(const ulonglong2*)&cW[j * 260 + k0];  // LDC.128
#pragma unroll
        for (int r = 0; r < RPT; r++) {
            fma2(accC[r][j], xq[r].x, w.x);
            fma2(accC[r][j], xq[r].y, w.y);
        }
    }
    // smem half: kp = k0/2 and k0/2+1, each row of sw8 = 8 u64 (j8..15)
    const ulonglong2* s0 = sw8v + (k0 >> 1) * 4;       // kp0: 4 ull2
    const ulonglong2* s1 = s0 + 4;                     // kp1
#pragma unroll
    for (int jj = 0; jj < 4; jj++) {
        ulonglong2 w0 = s0[jj];
        ulonglong2 w1 = s1[jj];
#pragma unroll
        for (int r = 0; r < RPT; r++) {
            fma2(accS[r][2 * jj],     xq[r].x, w0.x);
            fma2(accS[r][2 * jj + 1], xq[r].x, w0.y);
            fma2(accS[r][2 * jj],     xq[r].y, w1.x);
            fma2(accS[r][2 * jj + 1], xq[r].y, w1.y);
        }
    }
}

__global__ void __launch_bounds__(THREADS)
qlstm_kernel(const float* __restrict__ x, const float* __restrict__ hx,
             const float* __restrict__ cx,
             const float* __restrict__ Wu, const float* __restrict__ Wo,
             const float* __restrict__ bf, const float* __restrict__ bi,
             const float* __restrict__ bu, const float* __restrict__ bo,
             const float* __restrict__ tf, const float* __restrict__ ti,
             const float* __restrict__ tu, const float* __restrict__ to,
             float* __restrict__ out, int B)
{
    extern __shared__ float smem[];
    u64*   sw8    = (u64*)smem;                        // [130 kp][8 j] u64
    float* xs     = smem + SW8_U * 2;                  // [2 warps][2 stages][2304]
    float* sphase = xs + WARPS * 2 * XS_WARP_F;

    const int tid  = threadIdx.x;
    const int wid  = tid >> 5;
    const int lane = tid & 31;

    const int row0 = blockIdx.x * ROWS_BLK + wid * ROWS_WARP;
    const float* xw = x + (size_t)row0 * D_COLS;

    float* xs_w = xs + wid * (2 * XS_WARP_F);
    unsigned xs_s = (unsigned)__cvta_generic_to_shared(xs_w);

    // ---- prologue: this warp's tiles 0,1 ----
    issue_tile(xs_s, xw, lane, 0, 0);
    issue_tile(xs_s, xw, lane, 1, 1);

    // ---- stage smem half-weights (u,o gates, k-parity u64) + phases ----
    for (int i = tid; i < SW8_U; i += THREADS) {
        int kp = i >> 3, jj = i & 7;
        int w = jj & 3;
        const float* W = (jj < 4) ? Wu : Wo;
        sw8[i] = pk(W[w * 260 + 2 * kp], W[w * 260 + 2 * kp + 1]);
    }
    if (tid < NJ) {
        int j = tid, g = j >> 2, w = j & 3;
        const float* bb = (g == 0) ? bf : (g == 1) ? bi : (g == 2) ? bu : bo;
        const float* tt = (g == 0) ? tf : (g == 1) ? ti : (g == 2) ? tu : to;
        sphase[j] = bb[w] + tt[w];
    }
    __syncthreads();   // the ONLY block barrier

    const ulonglong2* sw8v = (const ulonglong2*)sw8;

    u64 accC[RPT][8], accS[RPT][8];
#pragma unroll
    for (int r = 0; r < RPT; r++)
#pragma unroll
        for (int j = 0; j < 8; j++) { accC[r][j] = 0ull; accS[r][j] = 0ull; }

    // ---- warp-private pipelined loop (prefetch after compute) ----
#pragma unroll 1
    for (int t = 0; t < NTILES; t++) {
        if (t == NTILES - 1) cp_wait0(); else cp_wait1();
        __syncwarp();

        const float* xb = xs_w + (t & 1) * XS_WARP_F;
#pragma unroll
        for (int kq = 0; kq < TILE_K / 4; kq++) {       // 8 float4-groups
            ulonglong2 xq[RPT];
#pragma unroll
            for (int rr = 0; rr < RPT; rr++)
                xq[rr] = *(const ulonglong2*)(xb + (lane + 32 * rr) * PITCH + kq * 4);
            do_group(accC, accS, xq, t * TILE_K + kq * 4, sw8v);
        }
        __syncwarp();

        if (t + 2 < NTILES)
            issue_tile(xs_s, xw, lane, t + 2, t & 1);
    }

    // ---- hx tail: k = 256..259 (kp 128,129; coalesced across lanes) ----
    {
        ulonglong2 xq[RPT];
#pragma unroll
        for (int rr = 0; rr < RPT; rr++)
            xq[rr] = ((const ulonglong2*)hx)[row0 + lane + 32 * rr];
        do_group(accC, accS, xq, 256, sw8v);
    }

    // ---- epilogue per row ----
#pragma unroll
    for (int rr = 0; rr < RPT; rr++) {
        int r = row0 + lane + 32 * rr;
        float z[NJ];
#pragma unroll
        for (int j = 0; j < 8; j++) {
            float lo, hi; upk(accC[rr][j], lo, hi);
            z[j] = __cosf(lo + hi + sphase[j]);
        }
#pragma unroll
        for (int j = 0; j < 8; j++) {
            float lo, hi; upk(accS[rr][j], lo, hi);
            z[8 + j] = __cosf(lo + hi + sphase[8 + j]);
        }
        float e[NJ];
#pragma unroll
        for (int g = 0; g < 4; g++) {
            float z0 = z[g*4+0], z1 = z[g*4+1], z2 = z[g*4+2], z3 = z[g*4+3];
            float p01 = z0 * z1;
            e[g*4+0] = z1 * z2 * z3;
            e[g*4+1] = p01;
            e[g*4+2] = p01 * z2;
            e[g*4+3] = p01 * z2 * z3;
        }
        float4 cxv = ((const float4*)cx)[r];
        float cxa[4] = {cxv.x, cxv.y, cxv.z, cxv.w};
        float hn[4], cn[4];
#pragma unroll
        for (int w = 0; w < 4; w++) {
            float fv = sigmoidf_(e[0*4+w]);
            float iv = sigmoidf_(e[1*4+w]);
            float gv = tanhf_(e[2*4+w]);
            float ov = sigmoidf_(e[3*4+w]);
            float c = fv * cxa[w] + iv * gv;
            cn[w] = c;
            hn[w] = ov * tanhf_(c);
        }
        ((float4*)out)[r] = make_float4(hn[0], hn[1], hn[2], hn[3]);
        ((float4*)(out + (size_t)B * 4))[r] = make_float4(cn[0], cn[1], cn[2], cn[3]);
    }
}

extern "C" void kernel_launch(void* const* d_in, const int* in_sizes, int n_in,
                              void* d_out, int out_size) {
    const float* x  = (const float*)d_in[0];
    const float* hx = (const float*)d_in[1];
    const float* cx = (const float*)d_in[2];
    const float* Wf = (const float*)d_in[3];
    const float* bf = (const float*)d_in[4];
    const float* Wi = (const float*)d_in[5];
    const float* bi = (const float*)d_in[6];
    const float* Wu = (const float*)d_in[7];
    const float* bu = (const float*)d_in[8];
    const float* Wo = (const float*)d_in[9];
    const float* bo = (const float*)d_in[10];
    const float* tf = (const float*)d_in[11];
    const float* ti = (const float*)d_in[12];
    const float* tu = (const float*)d_in[13];
    const float* to = (const float*)d_in[14];
    float* out = (float*)d_out;

    int B = in_sizes[0] / D_COLS;                 // 131072
    int grid = (B + ROWS_BLK - 1) / ROWS_BLK;     // 1024

    // raw weight images straight into constant memory (no repack kernel)
    cudaMemcpyToSymbolAsync(cW, Wf, 1040 * sizeof(float), 0,
                            cudaMemcpyDeviceToDevice);
    cudaMemcpyToSymbolAsync(cW, Wi, 1040 * sizeof(float), 1040 * sizeof(float),
                            cudaMemcpyDeviceToDevice);

    cudaFuncSetAttribute(qlstm_kernel,
                         cudaFuncAttributeMaxDynamicSharedMemorySize, SMEM_BYTES);
    qlstm_kernel<<<grid, THREADS, SMEM_BYTES>>>(
        x, hx, cx, Wu, Wo, bf, bi, bu, bo,
        tf, ti, tu, to, out, B);
}